// round 13
// baseline (speedup 1.0000x reference)
#include <cuda_runtime.h>
#include <cstdint>

#define BB 64
#define RR 32
#define NN 16384
#define DD 64
#define OO 8
#define SLICES 4
#define SN (NN / SLICES)       // 4096 elements per slice-block
#define TPB 512
#define NWARP 16
#define CAP 512                // per-slice hit capacity (expected ~30)

// Cross-block scratch. Zero at entry of every launch (.bss on call #1;
// last-arriving block per b self-cleans every call). NO fences anywhere:
// ordering via returning-ATOMG completion + STS-drain at barrier.
__device__ float g_s[BB * DD];
__device__ float g_cnt[BB];
__device__ int   g_arrive[BB];

__global__ void __launch_bounds__(TPB, 1) fused_kernel(
    const float* __restrict__ h_context,
    const float* __restrict__ l_local,
    const float* __restrict__ lambda_so,
    const int* __restrict__ center_o,
    const int* __restrict__ o_types,
    const unsigned int* __restrict__ adj,   // bool as 32-bit word (i32/f32 0|1)
    const unsigned int* __restrict__ two,
    float* __restrict__ out)
{
    __shared__ int   s_idx[CAP];
    __shared__ int   s_count;
    __shared__ float s_acc[DD];
    __shared__ int   s_last;
    volatile __shared__ float s_sink[16];

    const int b    = blockIdx.x >> 2;       // batch
    const int s    = blockIdx.x & 3;        // slice
    const int tid  = threadIdx.x;
    const int w    = tid >> 5;
    const int lane = tid & 31;

    if (tid == 0) s_count = 0;
    if (tid < DD) s_acc[tid] = 0.0f;

    const int co = __ldg(&center_o[b]);

    // ---- Phase A: streaming scan of slice (6 front-batched LDG.128) ----
    // uint4 index u = g*512 + tid (g in 0..1); element n = s*4096 + u*4 + j.
    const int base = b * NN + s * SN;
    const int4*  ot4 = reinterpret_cast<const int4*>(o_types + base);
    const uint4* a4  = reinterpret_cast<const uint4*>(adj + base);
    const uint4* t4  = reinterpret_cast<const uint4*>(two + base);

    int4  ot0 = ot4[tid];  int4  ot1 = ot4[tid + 512];
    uint4 a0  = a4[tid];   uint4 a1  = a4[tid + 512];
    uint4 t0  = t4[tid];   uint4 t1  = t4[tid + 512];

    unsigned hm = 0;
    hm |= (unsigned)((ot0.x == co) && (a0.x | t0.x)) << 0;
    hm |= (unsigned)((ot0.y == co) && (a0.y | t0.y)) << 1;
    hm |= (unsigned)((ot0.z == co) && (a0.z | t0.z)) << 2;
    hm |= (unsigned)((ot0.w == co) && (a0.w | t0.w)) << 3;
    hm |= (unsigned)((ot1.x == co) && (a1.x | t1.x)) << 4;
    hm |= (unsigned)((ot1.y == co) && (a1.y | t1.y)) << 5;
    hm |= (unsigned)((ot1.z == co) && (a1.z | t1.z)) << 6;
    hm |= (unsigned)((ot1.w == co) && (a1.w | t1.w)) << 7;
    __syncthreads();   // s_count / s_acc init visible

    // ---- Phase A2: compaction (~30 hitting threads per block) ----
    if (hm) {
        int p = atomicAdd(&s_count, __popc(hm));
        unsigned m = hm;
        while (m) {
            int k = __ffs(m) - 1; m &= m - 1;
            int n = s * SN + ((k >> 2) * 512 + tid) * 4 + (k & 3);
            if (p < CAP) s_idx[p] = n;
            p++;
        }
    }
    __syncthreads();

    const int cnt  = s_count;
    const int pcnt = (cnt < CAP) ? cnt : CAP;

    // ---- Phase B: warp-cooperative gather (2-row preload batches) ----
    const float2* ctx2 = reinterpret_cast<const float2*>(
        h_context + (size_t)b * NN * DD);
    float accx = 0.0f, accy = 0.0f;
    for (int bo = 0; bo < pcnt; bo += NWARP * 2) {
        float2 xs[2];
        #pragma unroll
        for (int k = 0; k < 2; k++) {
            int i = bo + k * NWARP + w;
            xs[k] = (i < pcnt)
                  ? __ldg(ctx2 + (size_t)s_idx[i] * (DD / 2) + lane)
                  : make_float2(0.0f, 0.0f);
        }
        #pragma unroll
        for (int k = 0; k < 2; k++) {
            float sq = xs[k].x * xs[k].x + xs[k].y * xs[k].y;
            #pragma unroll
            for (int o = 16; o; o >>= 1)
                sq += __shfl_xor_sync(0xffffffffu, sq, o);
            float rinv = rsqrtf(fmaxf(sq, 1e-12f));   // zero rows contribute 0
            accx += xs[k].x * rinv;
            accy += xs[k].y * rinv;
        }
    }
    atomicAdd(&s_acc[2 * lane + 0], accx);
    atomicAdd(&s_acc[2 * lane + 1], accy);
    __syncthreads();

    // ---- Publish partials: returning ATOMG -> STS sink -> barrier ----
    // STS operand depends on the ATOMG return, so reaching the barrier
    // proves every RMW is performed at L2. No fence needed.
    if (tid < DD) {
        float old = atomicAdd(&g_s[b * DD + tid], s_acc[tid]);
        s_sink[tid & 15] = old;
    }
    if (tid == DD) {
        float old = atomicAdd(&g_cnt[b], (float)cnt);
        s_sink[0] = old;
    }
    __syncthreads();

    if (tid == 0) {
        int prev = atomicAdd(&g_arrive[b], 1);
        s_last = (prev == SLICES - 1) ? 1 : 0;
    }
    __syncthreads();
    if (!s_last) return;

    // ---- Finalize (last-arriving block of this b) ----
    __shared__ float sv[DD];
    __shared__ float s_scnt;
    if (tid < DD) {
        sv[tid] = __ldcg(&g_s[b * DD + tid]);   // L2-coherent read
        g_s[b * DD + tid] = 0.0f;               // self-clean for next replay
    }
    if (tid == DD) { s_scnt = __ldcg(&g_cnt[b]); g_cnt[b] = 0.0f; }
    if (tid == 0)  g_arrive[b] = 0;             // restore replay invariant
    __syncthreads();

    const float cval = s_scnt;
    const float2* ll2 = reinterpret_cast<const float2*>(
        l_local + (size_t)b * RR * DD);
    #pragma unroll
    for (int rr = 0; rr < RR / NWARP; rr++) {
        int r = w + rr * NWARP;
        float2 x = __ldg(ll2 + (size_t)r * (DD / 2) + lane);
        float lam = __ldg(&lambda_so[r * OO + co]);
        float sq = x.x * x.x + x.y * x.y;
        float dp = x.x * sv[2 * lane] + x.y * sv[2 * lane + 1];
        #pragma unroll
        for (int o = 16; o; o >>= 1) {
            sq += __shfl_xor_sync(0xffffffffu, sq, o);
            dp += __shfl_xor_sync(0xffffffffu, dp, o);
        }
        if (lane == 0) {
            float rinv = rsqrtf(fmaxf(sq, 1e-12f));
            float avg = dp * rinv / fmaxf(cval, 1e-9f);
            float wv = fmaxf(lam / fmaxf(cval, 1.0f), 0.0f) * (1.0f - avg);
            out[b * RR + r] = wv;
        }
    }
}

extern "C" void kernel_launch(void* const* d_in, const int* in_sizes, int n_in,
                              void* d_out, int out_size) {
    const float*        l_local   = (const float*)d_in[0];
    const float*        h_context = (const float*)d_in[1];
    const float*        lambda_so = (const float*)d_in[2];
    const int*          center_o  = (const int*)d_in[3];
    const int*          o_types   = (const int*)d_in[4];
    const unsigned int* adj       = (const unsigned int*)d_in[5];
    const unsigned int* two       = (const unsigned int*)d_in[6];
    float*              out       = (float*)d_out;

    fused_kernel<<<BB * SLICES, TPB>>>(h_context, l_local, lambda_so,
                                       center_o, o_types, adj, two, out);
}

// round 14
// speedup vs baseline: 1.7022x; 1.7022x over previous
#include <cuda_runtime.h>
#include <cstdint>

#define BB 64
#define RR 32
#define NN 16384
#define DD 64
#define OO 8
#define TPB 1024
#define NWARP 32
#define WCAP 32                // per-warp hit capacity (mean ~3.8; P(>32) ~ 0)

// One block per b, 1024 threads, fully warp-local until the final combine.
// Phase A: streaming scan -> per-thread 16-bit hit mask (12 back-to-back
// LDG.128, no cross-lane ops). Phase A2: warp shfl-prefix compaction (ALU
// only). Phase B: warp gathers ITS OWN hits immediately (no block sync
// between scan and gather). Phase C: plain-store warp partials, one sync,
// 64-thread combine, epilogue (warp w == output row r).
__global__ void __launch_bounds__(TPB, 1) fused_kernel(
    const float* __restrict__ h_context,
    const float* __restrict__ l_local,
    const float* __restrict__ lambda_so,
    const int* __restrict__ center_o,
    const int* __restrict__ o_types,
    const unsigned int* __restrict__ adj,   // bool as 32-bit word (i32/f32 0|1)
    const unsigned int* __restrict__ two,
    float* __restrict__ out)
{
    __shared__ int   s_widx[NWARP][WCAP];
    __shared__ int   s_wcnt[NWARP];
    __shared__ float s_part[NWARP][DD];
    __shared__ float sv[DD];

    const int b    = blockIdx.x;
    const int tid  = threadIdx.x;
    const int w    = tid >> 5;     // warp id == output row r
    const int lane = tid & 31;

    // Epilogue operands resident early: thread tid's float2 of l_local[b]
    // is row (tid/32)=w, cols {2*lane, 2*lane+1}.
    const float2 ll = reinterpret_cast<const float2*>(
        l_local + (size_t)b * RR * DD)[tid];
    const int   co  = __ldg(&center_o[b]);
    const float lam = __ldg(&lambda_so[w * OO + co]);

    // ---- Phase A: streaming scan, private hit mask ----
    // uint4 index u = g*1024 + tid (g = 0..3); element n = g*4096 + tid*4 + j.
    const int4*  ot4 = reinterpret_cast<const int4*>(o_types + b * NN);
    const uint4* a4  = reinterpret_cast<const uint4*>(adj     + b * NN);
    const uint4* t4  = reinterpret_cast<const uint4*>(two     + b * NN);

    unsigned hm = 0;
    #pragma unroll
    for (int half = 0; half < 2; half++) {
        const int uA = (2 * half + 0) * 1024 + tid;
        const int uB = (2 * half + 1) * 1024 + tid;
        int4  otA = ot4[uA];  int4  otB = ot4[uB];
        uint4 aA  = a4[uA];   uint4 aB  = a4[uB];
        uint4 tA  = t4[uA];   uint4 tB  = t4[uB];

        unsigned gA = (2 * half + 0) * 4, gB = (2 * half + 1) * 4;
        hm |= (unsigned)((otA.x == co) && (aA.x | tA.x)) << (gA + 0);
        hm |= (unsigned)((otA.y == co) && (aA.y | tA.y)) << (gA + 1);
        hm |= (unsigned)((otA.z == co) && (aA.z | tA.z)) << (gA + 2);
        hm |= (unsigned)((otA.w == co) && (aA.w | tA.w)) << (gA + 3);
        hm |= (unsigned)((otB.x == co) && (aB.x | tB.x)) << (gB + 0);
        hm |= (unsigned)((otB.y == co) && (aB.y | tB.y)) << (gB + 1);
        hm |= (unsigned)((otB.z == co) && (aB.z | tB.z)) << (gB + 2);
        hm |= (unsigned)((otB.w == co) && (aB.w | tB.w)) << (gB + 3);
    }

    // ---- Phase A2: warp-local compaction (shfl prefix; no atomics) ----
    int my = __popc(hm);
    int pre = my;
    #pragma unroll
    for (int o = 1; o < 32; o <<= 1) {
        int v = __shfl_up_sync(0xffffffffu, pre, o);
        if (lane >= o) pre += v;
    }
    const int wtot = __shfl_sync(0xffffffffu, pre, 31);   // warp hit count
    int p = pre - my;                                      // exclusive prefix
    unsigned m = hm;
    while (m) {
        int k = __ffs(m) - 1; m &= m - 1;
        int n = (k >> 2) * 4096 + tid * 4 + (k & 3);
        if (p < WCAP) s_widx[w][p] = n;
        p++;
    }
    __syncwarp();
    const int wcnt = (wtot < WCAP) ? wtot : WCAP;

    // ---- Phase B: warp gathers its own hits (starts immediately) ----
    const float2* ctx2 = reinterpret_cast<const float2*>(
        h_context + (size_t)b * NN * DD);
    float accx = 0.0f, accy = 0.0f;
    for (int bo = 0; bo < wcnt; bo += 4) {
        float2 xs[4];
        #pragma unroll
        for (int k = 0; k < 4; k++) {
            int i = bo + k;
            xs[k] = (i < wcnt)
                  ? __ldg(ctx2 + (size_t)s_widx[w][i] * (DD / 2) + lane)
                  : make_float2(0.0f, 0.0f);
        }
        #pragma unroll
        for (int k = 0; k < 4; k++) {
            float sq = xs[k].x * xs[k].x + xs[k].y * xs[k].y;
            #pragma unroll
            for (int o = 16; o; o >>= 1)
                sq += __shfl_xor_sync(0xffffffffu, sq, o);
            float rinv = rsqrtf(fmaxf(sq, 1e-12f));   // zero rows contribute 0
            accx += xs[k].x * rinv;
            accy += xs[k].y * rinv;
        }
    }
    s_part[w][2 * lane + 0] = accx;
    s_part[w][2 * lane + 1] = accy;
    if (lane == 0) s_wcnt[w] = wtot;
    __syncthreads();

    // ---- Phase C: combine 32 warp partials (64 threads), then epilogue ----
    if (tid < DD) {
        float s = 0.0f;
        #pragma unroll
        for (int ww = 0; ww < NWARP; ww++) s += s_part[ww][tid];
        sv[tid] = s;
    }
    __syncthreads();

    int c = s_wcnt[lane];
    #pragma unroll
    for (int o = 16; o; o >>= 1) c += __shfl_xor_sync(0xffffffffu, c, o);
    const float cval = (float)c;

    float sq = ll.x * ll.x + ll.y * ll.y;
    float dp = ll.x * sv[2 * lane] + ll.y * sv[2 * lane + 1];
    #pragma unroll
    for (int o = 16; o; o >>= 1) {
        sq += __shfl_xor_sync(0xffffffffu, sq, o);
        dp += __shfl_xor_sync(0xffffffffu, dp, o);
    }
    if (lane == 0) {
        float rinv = rsqrtf(fmaxf(sq, 1e-12f));
        float avg = dp * rinv / fmaxf(cval, 1e-9f);
        float wv = fmaxf(lam / fmaxf(cval, 1.0f), 0.0f) * (1.0f - avg);
        out[b * RR + w] = wv;
    }
}

extern "C" void kernel_launch(void* const* d_in, const int* in_sizes, int n_in,
                              void* d_out, int out_size) {
    const float*        l_local   = (const float*)d_in[0];
    const float*        h_context = (const float*)d_in[1];
    const float*        lambda_so = (const float*)d_in[2];
    const int*          center_o  = (const int*)d_in[3];
    const int*          o_types   = (const int*)d_in[4];
    const unsigned int* adj       = (const unsigned int*)d_in[5];
    const unsigned int* two       = (const unsigned int*)d_in[6];
    float*              out       = (float*)d_out;

    fused_kernel<<<BB, TPB>>>(h_context, l_local, lambda_so,
                              center_o, o_types, adj, two, out);
}

// round 15
// speedup vs baseline: 1.7085x; 1.0037x over previous
#include <cuda_runtime.h>
#include <cstdint>

#define BB 64
#define RR 32
#define NN 16384
#define DD 64
#define OO 8
#define TPB 1024
#define NWARP 32
#define WCAP 32                 // per-warp hit capacity (mean ~3.8)
#define STAGES 4
#define SE (NN / STAGES)        // 4096 elements per stage
#define STAGE_BYTES (SE * 4)    // 16KB per array per stage

// Dynamic smem layout (bytes):
//   [0,       64K)   o_types   (4 stages x 16KB)
//   [64K,    128K)   adj
//   [128K,   192K)   two
//   [192K,   +256)   4 mbarriers (16B apart) + pad
#define SM_OT   0
#define SM_ADJ  (64 * 1024)
#define SM_TWO  (128 * 1024)
#define SM_MBAR (192 * 1024)
#define SM_TOTAL (192 * 1024 + 256)

__device__ __forceinline__ uint32_t smem_u32(const void* p) {
    return (uint32_t)__cvta_generic_to_shared(p);
}

__global__ void __launch_bounds__(TPB, 1) fused_kernel(
    const float* __restrict__ h_context,
    const float* __restrict__ l_local,
    const float* __restrict__ lambda_so,
    const int* __restrict__ center_o,
    const int* __restrict__ o_types,
    const unsigned int* __restrict__ adj,   // bool as 32-bit word (i32/f32 0|1)
    const unsigned int* __restrict__ two,
    float* __restrict__ out)
{
    extern __shared__ char smem[];
    __shared__ int   s_widx[NWARP][WCAP];
    __shared__ int   s_wcnt[NWARP];
    __shared__ float s_part[NWARP][DD];
    __shared__ float sv[DD];

    const int b    = blockIdx.x;
    const int tid  = threadIdx.x;
    const int w    = tid >> 5;     // warp id == output row r
    const int lane = tid & 31;

    // Epilogue operands resident early.
    const float2 ll = reinterpret_cast<const float2*>(
        l_local + (size_t)b * RR * DD)[tid];
    const int   co  = __ldg(&center_o[b]);
    const float lam = __ldg(&lambda_so[w * OO + co]);

    const uint32_t mbar0 = smem_u32(smem + SM_MBAR);

    // ---- Init mbarriers, then thread0 issues ALL bulk copies up front ----
    if (tid == 0) {
        #pragma unroll
        for (int s = 0; s < STAGES; s++) {
            uint32_t mb = mbar0 + s * 16;
            asm volatile("mbarrier.init.shared.b64 [%0], %1;"
                         :: "r"(mb), "r"(1) : "memory");
        }
    }
    __syncthreads();

    if (tid == 0) {
        const char* g_ot  = (const char*)(o_types + b * NN);
        const char* g_adj = (const char*)(adj     + b * NN);
        const char* g_two = (const char*)(two     + b * NN);
        #pragma unroll
        for (int s = 0; s < STAGES; s++) {
            uint32_t mb = mbar0 + s * 16;
            asm volatile("mbarrier.arrive.expect_tx.shared.b64 _, [%0], %1;"
                         :: "r"(mb), "r"(3 * STAGE_BYTES) : "memory");
            uint32_t d0 = smem_u32(smem + SM_OT  + s * STAGE_BYTES);
            uint32_t d1 = smem_u32(smem + SM_ADJ + s * STAGE_BYTES);
            uint32_t d2 = smem_u32(smem + SM_TWO + s * STAGE_BYTES);
            asm volatile("cp.async.bulk.shared::cta.global.mbarrier::complete_tx::bytes [%0], [%1], %2, [%3];"
                         :: "r"(d0), "l"(g_ot  + s * STAGE_BYTES), "r"(STAGE_BYTES), "r"(mb) : "memory");
            asm volatile("cp.async.bulk.shared::cta.global.mbarrier::complete_tx::bytes [%0], [%1], %2, [%3];"
                         :: "r"(d1), "l"(g_adj + s * STAGE_BYTES), "r"(STAGE_BYTES), "r"(mb) : "memory");
            asm volatile("cp.async.bulk.shared::cta.global.mbarrier::complete_tx::bytes [%0], [%1], %2, [%3];"
                         :: "r"(d2), "l"(g_two + s * STAGE_BYTES), "r"(STAGE_BYTES), "r"(mb) : "memory");
        }
    }

    // ---- Staged scan from smem + warp-local compaction ----
    const int4*  sot = reinterpret_cast<const int4*>(smem + SM_OT);
    const uint4* sad = reinterpret_cast<const uint4*>(smem + SM_ADJ);
    const uint4* stw = reinterpret_cast<const uint4*>(smem + SM_TWO);

    int wbase = 0;   // running warp hit count (warp-uniform)
    #pragma unroll
    for (int s = 0; s < STAGES; s++) {
        // Wait stage s (acquire).
        {
            uint32_t mb = mbar0 + s * 16;
            uint32_t done;
            asm volatile(
                "{\n\t.reg .pred p;\n\t"
                "mbarrier.try_wait.parity.acquire.cta.shared::cta.b64 p, [%1], %2;\n\t"
                "selp.b32 %0, 1, 0, p;\n\t}"
                : "=r"(done) : "r"(mb), "r"(0) : "memory");
            while (!done) {
                asm volatile(
                    "{\n\t.reg .pred p;\n\t"
                    "mbarrier.try_wait.parity.acquire.cta.shared::cta.b64 p, [%1], %2, 0x989680;\n\t"
                    "selp.b32 %0, 1, 0, p;\n\t}"
                    : "=r"(done) : "r"(mb), "r"(0) : "memory");
            }
        }

        // Scan: 4096 elements / 1024 threads = 1 int4 per array per thread.
        int u = s * (SE / 4) + tid;
        int4  ot = sot[u];
        uint4 a  = sad[u];
        uint4 t  = stw[u];
        unsigned hm = 0;
        hm |= (unsigned)((ot.x == co) && (a.x | t.x)) << 0;
        hm |= (unsigned)((ot.y == co) && (a.y | t.y)) << 1;
        hm |= (unsigned)((ot.z == co) && (a.z | t.z)) << 2;
        hm |= (unsigned)((ot.w == co) && (a.w | t.w)) << 3;

        // Warp prefix over hit counts; append to warp list.
        int my = __popc(hm);
        int pre = my;
        #pragma unroll
        for (int o = 1; o < 32; o <<= 1) {
            int v = __shfl_up_sync(0xffffffffu, pre, o);
            if (lane >= o) pre += v;
        }
        int wtot = __shfl_sync(0xffffffffu, pre, 31);
        int p = wbase + pre - my;
        unsigned m = hm;
        while (m) {
            int k = __ffs(m) - 1; m &= m - 1;
            int n = s * SE + tid * 4 + k - (w * 32 - w * 32); // n within b
            n = s * SE + ((tid) * 4) + k;
            if (p < WCAP) s_widx[w][p] = n;
            p++;
        }
        wbase += wtot;
        __syncwarp();
    }
    const int wcnt = (wbase < WCAP) ? wbase : WCAP;

    // ---- Gather + normalize (warp-local, 4-row preload batches) ----
    const float2* ctx2 = reinterpret_cast<const float2*>(
        h_context + (size_t)b * NN * DD);
    float accx = 0.0f, accy = 0.0f;
    for (int bo = 0; bo < wcnt; bo += 4) {
        float2 xs[4];
        #pragma unroll
        for (int k = 0; k < 4; k++) {
            int i = bo + k;
            xs[k] = (i < wcnt)
                  ? __ldg(ctx2 + (size_t)s_widx[w][i] * (DD / 2) + lane)
                  : make_float2(0.0f, 0.0f);
        }
        #pragma unroll
        for (int k = 0; k < 4; k++) {
            float sq = xs[k].x * xs[k].x + xs[k].y * xs[k].y;
            #pragma unroll
            for (int o = 16; o; o >>= 1)
                sq += __shfl_xor_sync(0xffffffffu, sq, o);
            float rinv = rsqrtf(fmaxf(sq, 1e-12f));   // zero rows contribute 0
            accx += xs[k].x * rinv;
            accy += xs[k].y * rinv;
        }
    }
    s_part[w][2 * lane + 0] = accx;
    s_part[w][2 * lane + 1] = accy;
    if (lane == 0) s_wcnt[w] = wbase;
    __syncthreads();

    // ---- Combine + epilogue (warp w == row r) ----
    if (tid < DD) {
        float s = 0.0f;
        #pragma unroll
        for (int ww = 0; ww < NWARP; ww++) s += s_part[ww][tid];
        sv[tid] = s;
    }
    __syncthreads();

    int c = s_wcnt[lane];
    #pragma unroll
    for (int o = 16; o; o >>= 1) c += __shfl_xor_sync(0xffffffffu, c, o);
    const float cval = (float)c;

    float sq = ll.x * ll.x + ll.y * ll.y;
    float dp = ll.x * sv[2 * lane] + ll.y * sv[2 * lane + 1];
    #pragma unroll
    for (int o = 16; o; o >>= 1) {
        sq += __shfl_xor_sync(0xffffffffu, sq, o);
        dp += __shfl_xor_sync(0xffffffffu, dp, o);
    }
    if (lane == 0) {
        float rinv = rsqrtf(fmaxf(sq, 1e-12f));
        float avg = dp * rinv / fmaxf(cval, 1e-9f);
        float wv = fmaxf(lam / fmaxf(cval, 1.0f), 0.0f) * (1.0f - avg);
        out[b * RR + w] = wv;
    }
}

extern "C" void kernel_launch(void* const* d_in, const int* in_sizes, int n_in,
                              void* d_out, int out_size) {
    const float*        l_local   = (const float*)d_in[0];
    const float*        h_context = (const float*)d_in[1];
    const float*        lambda_so = (const float*)d_in[2];
    const int*          center_o  = (const int*)d_in[3];
    const int*          o_types   = (const int*)d_in[4];
    const unsigned int* adj       = (const unsigned int*)d_in[5];
    const unsigned int* two       = (const unsigned int*)d_in[6];
    float*              out       = (float*)d_out;

    cudaFuncSetAttribute(fused_kernel,
                         cudaFuncAttributeMaxDynamicSharedMemorySize, SM_TOTAL);
    fused_kernel<<<BB, TPB, SM_TOTAL>>>(h_context, l_local, lambda_so,
                                        center_o, o_types, adj, two, out);
}